// round 1
// baseline (speedup 1.0000x reference)
#include <cuda_runtime.h>

#define N_MSG 16384
#define NNB 10
#define IN_F 135
#define H 256
#define HEADS 4
#define DPH 64
#define DEPTH 5
#define NEG_INF -1e18f

// ---------------- scratch (static device globals; no allocation) ------------
__device__ float g_h[N_MSG * H];          // hidden state
__device__ float g_KV[N_MSG * 2 * H];     // [K | V] per row
__device__ float g_sumh[N_MSG * H];       // attention output
__device__ float g_T[N_MSG * 2 * H];      // [sum_h@Wz2^T | sum_h@Ur^T]
__device__ float g_z[N_MSG * H];          // gate z
__device__ float g_rs[N_MSG * H];         // r * sum_h
__device__ float g_F[N_MSG * 3 * H];      // [fz | fr | fh] (loop-invariant)
__device__ float g_P[N_MSG * H];          // reused: q pre / pre_h gemm out
__device__ float g_qs[N_MSG * HEADS];     // q-part of score
__device__ float g_ks[N_MSG * HEADS];     // k-part of score (per step)
__device__ float g_rowsum[N_MSG];         // sum(h[n,:]) for mask
// packed weights (transposed to [K, Nout] row-major)
__device__ float g_Wkv[H * 2 * H];
__device__ float g_Wzr[H * 2 * H];
__device__ float g_Wh2[H * H];
__device__ float g_Wf[IN_F * 3 * H];
__device__ float g_Wqp[IN_F * H];
__device__ float g_bkv[2 * H];
__device__ float g_bf[3 * H];

// ---------------- weight packing (cheap, once per launch) -------------------
__global__ void pack_all(const float* __restrict__ Wq,
                         const float* __restrict__ Wk, const float* __restrict__ bk,
                         const float* __restrict__ Wv, const float* __restrict__ bv,
                         const float* __restrict__ Wz, const float* __restrict__ bz,
                         const float* __restrict__ Wr, const float* __restrict__ Ur,
                         const float* __restrict__ bur,
                         const float* __restrict__ Wh, const float* __restrict__ bh) {
    int i = blockIdx.x * blockDim.x + threadIdx.x;
    const int WIDE = IN_F + H;  // 391
    if (i < H * 2 * H) {
        int k = i / (2 * H), o = i % (2 * H);
        g_Wkv[i] = (o < H) ? Wk[o * H + k] : Wv[(o - H) * H + k];
        g_Wzr[i] = (o < H) ? Wz[o * WIDE + IN_F + k] : Ur[(o - H) * H + k];
    }
    if (i < H * H) {
        int k = i / H, o = i % H;
        g_Wh2[i] = Wh[o * WIDE + IN_F + k];
    }
    if (i < IN_F * 3 * H) {
        int k = i / (3 * H), o = i % (3 * H);
        g_Wf[i] = (o < H) ? Wz[o * WIDE + k]
                : (o < 2 * H) ? Wr[(o - H) * IN_F + k]
                : Wh[(o - 2 * H) * WIDE + k];
    }
    if (i < IN_F * H) {
        int k = i / H, o = i % H;
        g_Wqp[i] = Wq[o * IN_F + k];
    }
    if (i < 2 * H) g_bkv[i] = (i < H) ? bk[i] : bv[i - H];
    if (i < 3 * H) g_bf[i] = (i < H) ? bz[i] : (i < 2 * H ? bur[i - H] : bh[i - 2 * H]);
}

// ---------------- generic fp32 GEMM: C[M,Nc] = A[M,Kd] * B[Kd,Nc] + bias ----
// 64x64 block tile, 256 threads, 4x4 per-thread micro-tile, K-tile 16.
__global__ __launch_bounds__(256)
void gemm64(const float* __restrict__ A, int lda,
            const float* __restrict__ B,
            const float* __restrict__ bias,
            float* __restrict__ C, int ldc,
            int Kdim, int Ncols) {
    __shared__ float As[16][65];
    __shared__ float Bs[16][65];
    int tid = threadIdx.x;
    int tx = tid & 15, ty = tid >> 4;
    int row0 = blockIdx.y * 64, col0 = blockIdx.x * 64;
    float acc[4][4] = {};
    for (int k0 = 0; k0 < Kdim; k0 += 16) {
#pragma unroll
        for (int p = 0; p < 4; p++) {
            int e = tid + 256 * p;
            int r = e >> 4, k = e & 15;
            float v = 0.f;
            if (k0 + k < Kdim) v = A[(size_t)(row0 + r) * lda + k0 + k];
            As[k][r] = v;
        }
#pragma unroll
        for (int p = 0; p < 4; p++) {
            int e = tid + 256 * p;
            int k = e >> 6, c = e & 63;
            float v = 0.f;
            if (k0 + k < Kdim) v = B[(size_t)(k0 + k) * Ncols + col0 + c];
            Bs[k][c] = v;
        }
        __syncthreads();
#pragma unroll
        for (int k = 0; k < 16; k++) {
            float a[4], b[4];
#pragma unroll
            for (int i = 0; i < 4; i++) a[i] = As[k][ty * 4 + i];
#pragma unroll
            for (int j = 0; j < 4; j++) b[j] = Bs[k][tx * 4 + j];
#pragma unroll
            for (int i = 0; i < 4; i++)
#pragma unroll
                for (int j = 0; j < 4; j++) acc[i][j] += a[i] * b[j];
        }
        __syncthreads();
    }
#pragma unroll
    for (int i = 0; i < 4; i++) {
#pragma unroll
        for (int j = 0; j < 4; j++) {
            int c = col0 + tx * 4 + j;
            float v = acc[i][j];
            if (bias) v += bias[c];
            C[(size_t)(row0 + ty * 4 + i) * ldc + c] = v;
        }
    }
}

// ---------------- qscore: per-row reduce of lrelu(Q)·alpha[:, :64] ----------
__global__ void qscore_kernel(const float* __restrict__ alpha) {
    int warp = threadIdx.x >> 5, lane = threadIdx.x & 31;
    int n = blockIdx.x * 8 + warp;
    float acc[4] = {0.f, 0.f, 0.f, 0.f};
#pragma unroll
    for (int tt = 0; tt < 8; tt++) {
        int c = lane + 32 * tt;      // head = tt>>1
        float v = g_P[(size_t)n * H + c];
        float lr = v >= 0.f ? v : 0.01f * v;
        acc[tt >> 1] += lr * alpha[(tt >> 1) * 128 + (c & 63)];
    }
#pragma unroll
    for (int hh = 0; hh < 4; hh++)
        for (int o = 16; o; o >>= 1)
            acc[hh] += __shfl_xor_sync(0xffffffffu, acc[hh], o);
    if (lane == 0) {
#pragma unroll
        for (int hh = 0; hh < 4; hh++) g_qs[n * 4 + hh] = acc[hh];
    }
}

// ---------------- per-step: kscore (lrelu(K)·alpha[:,64:]) + rowsum(h) ------
__global__ void prep_kernel(const float* __restrict__ alpha) {
    int warp = threadIdx.x >> 5, lane = threadIdx.x & 31;
    int n = blockIdx.x * 8 + warp;
    float rs = 0.f;
    float acc[4] = {0.f, 0.f, 0.f, 0.f};
#pragma unroll
    for (int tt = 0; tt < 8; tt++) {
        int c = lane + 32 * tt;
        rs += g_h[(size_t)n * H + c];
        float v = g_KV[(size_t)n * (2 * H) + c];
        float lr = v >= 0.f ? v : 0.01f * v;
        acc[tt >> 1] += lr * alpha[(tt >> 1) * 128 + 64 + (c & 63)];
    }
    for (int o = 16; o; o >>= 1) {
        rs += __shfl_xor_sync(0xffffffffu, rs, o);
#pragma unroll
        for (int hh = 0; hh < 4; hh++)
            acc[hh] += __shfl_xor_sync(0xffffffffu, acc[hh], o);
    }
    if (lane == 0) {
        g_rowsum[n] = rs;
#pragma unroll
        for (int hh = 0; hh < 4; hh++) g_ks[n * 4 + hh] = acc[hh];
    }
}

// ---------------- attention: scores -> softmax(10) -> weighted V gather -----
__global__ __launch_bounds__(256)
void attn_kernel(const int* __restrict__ bgraph, const float* __restrict__ abias) {
    int n = blockIdx.x;
    int t = threadIdx.x;
    __shared__ int js[NNB];
    __shared__ float sc[NNB][HEADS];
    __shared__ float wgt[NNB][HEADS];
    if (t < NNB) js[t] = bgraph[n * NNB + t];
    __syncthreads();
    if (t < NNB * HEADS) {
        int m = t >> 2, hh = t & 3;
        int j = js[m];
        float s = g_qs[n * 4 + hh] + g_ks[j * 4 + hh] + abias[hh];
        if (g_rowsum[j] == 0.0f) s = NEG_INF;
        sc[m][hh] = s;
    }
    __syncthreads();
    if (t < HEADS) {
        float mx = -INFINITY;
#pragma unroll
        for (int m = 0; m < NNB; m++) mx = fmaxf(mx, sc[m][t]);
        float e[NNB], ssum = 0.f;
#pragma unroll
        for (int m = 0; m < NNB; m++) { e[m] = expf(sc[m][t] - mx); ssum += e[m]; }
        float inv = 1.0f / ssum;
#pragma unroll
        for (int m = 0; m < NNB; m++) wgt[m][t] = e[m] * inv;
    }
    __syncthreads();
    int hh = t >> 6;
    float acc = 0.f;
#pragma unroll
    for (int m = 0; m < NNB; m++)
        acc += wgt[m][hh] * g_KV[(size_t)js[m] * (2 * H) + H + t];
    g_sumh[(size_t)n * H + t] = acc;
}

// ---------------- epilogues -------------------------------------------------
__device__ __forceinline__ float sigmoidf_(float x) { return 1.0f / (1.0f + expf(-x)); }

__global__ void zr_epilogue() {
    int i = blockIdx.x * blockDim.x + threadIdx.x;   // i over N*H
    int n = i >> 8, c = i & 255;
    float z = sigmoidf_(g_F[(size_t)n * 768 + c] + g_T[(size_t)n * 512 + c]);
    float r = sigmoidf_(g_F[(size_t)n * 768 + 256 + c] + g_T[(size_t)n * 512 + 256 + c]);
    g_z[i] = z;
    g_rs[i] = r * g_sumh[i];
}

__global__ void final_epilogue(float* __restrict__ dst) {
    int i = blockIdx.x * blockDim.x + threadIdx.x;
    int n = i >> 8, c = i & 255;
    float pre = tanhf(g_F[(size_t)n * 768 + 512 + c] + g_P[i]);
    float z = g_z[i];
    float s = g_sumh[i];
    float nh = (1.0f - z) * s + z * pre;
    dst[i] = (n == 0) ? 0.0f : nh;
}

// ---------------- launch -----------------------------------------------------
static float* symaddr(const void* s) {
    void* p = nullptr;
    cudaGetSymbolAddress(&p, s);
    return (float*)p;
}

extern "C" void kernel_launch(void* const* d_in, const int* in_sizes, int n_in,
                              void* d_out, int out_size) {
    const float* fmess = (const float*)d_in[0];
    const int*   bgraph = (const int*)d_in[1];
    const float* Wq = (const float*)d_in[2];
    const float* bq = (const float*)d_in[3];
    const float* Wk = (const float*)d_in[4];
    const float* bk = (const float*)d_in[5];
    const float* Wv = (const float*)d_in[6];
    const float* bv = (const float*)d_in[7];
    const float* alpha = (const float*)d_in[8];
    const float* abias = (const float*)d_in[9];
    const float* Wz = (const float*)d_in[10];
    const float* bz = (const float*)d_in[11];
    const float* Wr = (const float*)d_in[12];
    const float* Ur = (const float*)d_in[13];
    const float* bur = (const float*)d_in[14];
    const float* Wh = (const float*)d_in[15];
    const float* bh = (const float*)d_in[16];
    float* out = (float*)d_out;

    float* p_h   = symaddr(g_h);
    float* p_KV  = symaddr(g_KV);
    float* p_sumh= symaddr(g_sumh);
    float* p_T   = symaddr(g_T);
    float* p_rs  = symaddr(g_rs);
    float* p_F   = symaddr(g_F);
    float* p_P   = symaddr(g_P);
    float* p_Wkv = symaddr(g_Wkv);
    float* p_Wzr = symaddr(g_Wzr);
    float* p_Wh2 = symaddr(g_Wh2);
    float* p_Wf  = symaddr(g_Wf);
    float* p_Wqp = symaddr(g_Wqp);
    float* p_bkv = symaddr(g_bkv);
    float* p_bf  = symaddr(g_bf);

    cudaMemsetAsync(p_h, 0, (size_t)N_MSG * H * sizeof(float), 0);

    pack_all<<<512, 256>>>(Wq, Wk, bk, Wv, bv, Wz, bz, Wr, Ur, bur, Wh, bh);

    // loop-invariant precompute: F = fmess @ [Wz1|Wr|Wh1]^T + [bz|bur|bh]
    gemm64<<<dim3(768 / 64, N_MSG / 64), 256>>>(fmess, IN_F, p_Wf, p_bf, p_F, 768, IN_F, 768);
    // Q = fmess @ Wq^T + bq  (into g_P), then reduce to qscore
    gemm64<<<dim3(H / 64, N_MSG / 64), 256>>>(fmess, IN_F, p_Wqp, bq, p_P, H, IN_F, H);
    qscore_kernel<<<N_MSG / 8, 256>>>(alpha);

    for (int step = 0; step < DEPTH; step++) {
        // K|V = h @ [Wk|Wv]^T + [bk|bv]
        gemm64<<<dim3(512 / 64, N_MSG / 64), 256>>>(p_h, H, p_Wkv, p_bkv, p_KV, 512, H, 512);
        prep_kernel<<<N_MSG / 8, 256>>>(alpha);
        attn_kernel<<<N_MSG, 256>>>(bgraph, abias);
        // T = sum_h @ [Wz2|Ur]^T
        gemm64<<<dim3(512 / 64, N_MSG / 64), 256>>>(p_sumh, H, p_Wzr, nullptr, p_T, 512, H, 512);
        zr_epilogue<<<N_MSG * H / 256, 256>>>();
        // P = (r*sum_h) @ Wh2^T
        gemm64<<<dim3(H / 64, N_MSG / 64), 256>>>(p_rs, H, p_Wh2, nullptr, p_P, H, H, H);
        final_epilogue<<<N_MSG * H / 256, 256>>>(step == DEPTH - 1 ? out : p_h);
    }
    (void)in_sizes; (void)n_in; (void)out_size;
}

// round 3
// speedup vs baseline: 1.4373x; 1.4373x over previous
#include <cuda_runtime.h>

#define N_MSG 16384
#define NNB 10
#define IN_F 135
#define KPAD 144
#define H 256
#define HEADS 4
#define DEPTH 5
#define NEG_INF -1e18f

// ---------------- scratch (static device globals; no allocation) ------------
__device__ float g_h[N_MSG * H];          // hidden state
__device__ float g_KV[N_MSG * 2 * H];     // [K | V] per row
__device__ float g_sumh[N_MSG * H];       // attention output
__device__ float g_z[N_MSG * H];          // gate z
__device__ float g_rs[N_MSG * H];         // r * sum_h
__device__ float g_F[N_MSG * 3 * H];      // [fz | fr | fh] (loop-invariant)
__device__ float g_P[N_MSG * H];          // q pre-activation (one-time)
__device__ float g_qs[N_MSG * HEADS];     // q-part of score
__device__ float g_ks[N_MSG * HEADS];     // k-part of score (per step)
__device__ float g_rowsum[N_MSG];         // sum(h[n,:]) for mask
__device__ float g_fpad[N_MSG * KPAD];    // fmess padded to K=144
// packed weights (transposed to [K, Nout] row-major)
__device__ float g_Wkv[H * 2 * H];
__device__ float g_Wzr[H * 2 * H];
__device__ float g_Wh2[H * H];
__device__ float g_Wf[KPAD * 3 * H];
__device__ float g_Wqp[KPAD * H];
__device__ float g_bkv[2 * H];
__device__ float g_bf[3 * H];

// ---------------- fmess padding ---------------------------------------------
__global__ void pad_fmess(const float* __restrict__ fmess) {
    int i = blockIdx.x * blockDim.x + threadIdx.x;
    if (i >= N_MSG * KPAD) return;
    int n = i / KPAD, c = i % KPAD;
    g_fpad[i] = (c < IN_F) ? fmess[n * IN_F + c] : 0.0f;
}

// ---------------- weight packing (cheap, once per launch) -------------------
// NOTE: must be launched with >= H*2*H (=131072) threads. (R2 bug: was 110592.)
__global__ void pack_all(const float* __restrict__ Wq,
                         const float* __restrict__ Wk, const float* __restrict__ bk,
                         const float* __restrict__ Wv, const float* __restrict__ bv,
                         const float* __restrict__ Wz, const float* __restrict__ bz,
                         const float* __restrict__ Wr, const float* __restrict__ Ur,
                         const float* __restrict__ bur,
                         const float* __restrict__ Wh, const float* __restrict__ bh) {
    int i = blockIdx.x * blockDim.x + threadIdx.x;
    const int WIDE = IN_F + H;  // 391
    if (i < H * 2 * H) {
        int k = i / (2 * H), o = i % (2 * H);
        g_Wkv[i] = (o < H) ? Wk[o * H + k] : Wv[(o - H) * H + k];
        g_Wzr[i] = (o < H) ? Wz[o * WIDE + IN_F + k] : Ur[(o - H) * H + k];
    }
    if (i < H * H) {
        int k = i / H, o = i % H;
        g_Wh2[i] = Wh[o * WIDE + IN_F + k];
    }
    if (i < KPAD * 3 * H) {
        int k = i / (3 * H), o = i % (3 * H);
        float v = 0.0f;
        if (k < IN_F)
            v = (o < H) ? Wz[o * WIDE + k]
              : (o < 2 * H) ? Wr[(o - H) * IN_F + k]
              : Wh[(o - 2 * H) * WIDE + k];
        g_Wf[i] = v;
    }
    if (i < KPAD * H) {
        int k = i / H, o = i % H;
        g_Wqp[i] = (k < IN_F) ? Wq[o * IN_F + k] : 0.0f;
    }
    if (i < 2 * H) g_bkv[i] = (i < H) ? bk[i] : bv[i - H];
    if (i < 3 * H) g_bf[i] = (i < H) ? bz[i] : (i < 2 * H ? bur[i - H] : bh[i - 2 * H]);
}

// ---------------- packed f32x2 FMA ------------------------------------------
__device__ __forceinline__ void ffma2(float2& d, const float2& a, const float2& b) {
    asm("fma.rn.f32x2 %0, %1, %2, %0;"
        : "+l"(reinterpret_cast<unsigned long long&>(d))
        : "l"(reinterpret_cast<const unsigned long long&>(a)),
          "l"(reinterpret_cast<const unsigned long long&>(b)));
}

__device__ __forceinline__ float sigmoidf_(float x) { return 1.0f / (1.0f + expf(-x)); }

// ---------------- fused 128x128 fp32 GEMM (FFMA2 inner loop) -----------------
// C[M,N] = A[M,K] * B[K,N]; modes fuse the GRU epilogues.
#define BM 128
#define BN 128
#define BK 16
#define MODE_PLAIN 0
#define MODE_ZR 1
#define MODE_FINAL 2

__global__ __launch_bounds__(256, 2)
void gemm128(const float* __restrict__ A, int lda,
             const float* __restrict__ B, int ldb,
             const float* __restrict__ bias,
             float* __restrict__ C,
             int Kdim, int mode, float* __restrict__ dst) {
    __shared__ float As[2][BK][BM + 4];
    __shared__ float Bs[2][BK][BN];

    const int tid = threadIdx.x;
    const int tx = tid & 15, ty = tid >> 4;
    const int row0 = blockIdx.y * BM, col0 = blockIdx.x * BN;

    const int arow = tid >> 2;            // 0..63
    const int akq  = (tid & 3) << 2;      // 0,4,8,12
    const int brow = tid >> 5;            // 0..7
    const int bc4  = (tid & 31) << 2;     // 0..124

    float4 ra0, ra1, rb0, rb1;

    auto gload = [&](int k0) {
        ra0 = *(const float4*)&A[(size_t)(row0 + arow) * lda + k0 + akq];
        ra1 = *(const float4*)&A[(size_t)(row0 + 64 + arow) * lda + k0 + akq];
        rb0 = *(const float4*)&B[(size_t)(k0 + brow) * ldb + col0 + bc4];
        rb1 = *(const float4*)&B[(size_t)(k0 + 8 + brow) * ldb + col0 + bc4];
    };
    auto sstore = [&](int buf) {
        As[buf][akq + 0][arow] = ra0.x;
        As[buf][akq + 1][arow] = ra0.y;
        As[buf][akq + 2][arow] = ra0.z;
        As[buf][akq + 3][arow] = ra0.w;
        As[buf][akq + 0][arow + 64] = ra1.x;
        As[buf][akq + 1][arow + 64] = ra1.y;
        As[buf][akq + 2][arow + 64] = ra1.z;
        As[buf][akq + 3][arow + 64] = ra1.w;
        *(float4*)&Bs[buf][brow][bc4] = rb0;
        *(float4*)&Bs[buf][8 + brow][bc4] = rb1;
    };

    float2 acc[8][4];
#pragma unroll
    for (int i = 0; i < 8; i++)
#pragma unroll
        for (int j = 0; j < 4; j++) acc[i][j] = make_float2(0.f, 0.f);

    gload(0);
    sstore(0);
    __syncthreads();

    const int ntiles = Kdim / BK;
    for (int t = 0; t < ntiles; t++) {
        if (t + 1 < ntiles) gload((t + 1) * BK);
        const int buf = t & 1;
#pragma unroll
        for (int k = 0; k < BK; k++) {
            float4 a0 = *(const float4*)&As[buf][k][ty * 4];
            float4 a1 = *(const float4*)&As[buf][k][64 + ty * 4];
            float4 b0 = *(const float4*)&Bs[buf][k][tx * 4];
            float4 b1 = *(const float4*)&Bs[buf][k][64 + tx * 4];
            float ar[8] = {a0.x, a0.y, a0.z, a0.w, a1.x, a1.y, a1.z, a1.w};
            float2 bc[4] = {{b0.x, b0.y}, {b0.z, b0.w}, {b1.x, b1.y}, {b1.z, b1.w}};
#pragma unroll
            for (int i = 0; i < 8; i++) {
                float2 aa = make_float2(ar[i], ar[i]);
#pragma unroll
                for (int j = 0; j < 4; j++) ffma2(acc[i][j], aa, bc[j]);
            }
        }
        if (t + 1 < ntiles) {
            sstore((t + 1) & 1);
            __syncthreads();
        }
    }

    // ---------------- epilogue ----------------
#pragma unroll
    for (int i = 0; i < 8; i++) {
        int r = row0 + ((i < 4) ? (ty * 4 + i) : (64 + ty * 4 + i - 4));
#pragma unroll
        for (int half = 0; half < 2; half++) {
            int c = col0 + half * 64 + tx * 4;           // global col of 4-wide chunk
            float4 v;
            v.x = acc[i][half * 2 + 0].x;
            v.y = acc[i][half * 2 + 0].y;
            v.z = acc[i][half * 2 + 1].x;
            v.w = acc[i][half * 2 + 1].y;
            if (mode == MODE_PLAIN) {
                if (bias) {
                    float4 bb = *(const float4*)&bias[c];
                    v.x += bb.x; v.y += bb.y; v.z += bb.z; v.w += bb.w;
                }
                *(float4*)&C[(size_t)r * ldb + c] = v;
            } else if (mode == MODE_ZR) {
                if (c < 256) {
                    // z = sigmoid(Fz + sum_h@Wz2^T)
                    float4 f = *(const float4*)&g_F[(size_t)r * 768 + c];
                    float4 zo;
                    zo.x = sigmoidf_(f.x + v.x);
                    zo.y = sigmoidf_(f.y + v.y);
                    zo.z = sigmoidf_(f.z + v.z);
                    zo.w = sigmoidf_(f.w + v.w);
                    *(float4*)&g_z[(size_t)r * 256 + c] = zo;
                } else {
                    int cc = c - 256;
                    // r = sigmoid(Fr + sum_h@Ur^T); rs = r * sum_h
                    float4 f = *(const float4*)&g_F[(size_t)r * 768 + 256 + cc];
                    float4 s = *(const float4*)&g_sumh[(size_t)r * 256 + cc];
                    float4 ro;
                    ro.x = sigmoidf_(f.x + v.x) * s.x;
                    ro.y = sigmoidf_(f.y + v.y) * s.y;
                    ro.z = sigmoidf_(f.z + v.z) * s.z;
                    ro.w = sigmoidf_(f.w + v.w) * s.w;
                    *(float4*)&g_rs[(size_t)r * 256 + cc] = ro;
                }
            } else {  // MODE_FINAL
                float4 f = *(const float4*)&g_F[(size_t)r * 768 + 512 + c];
                float4 zz = *(const float4*)&g_z[(size_t)r * 256 + c];
                float4 ss = *(const float4*)&g_sumh[(size_t)r * 256 + c];
                float4 o;
                o.x = (1.0f - zz.x) * ss.x + zz.x * tanhf(f.x + v.x);
                o.y = (1.0f - zz.y) * ss.y + zz.y * tanhf(f.y + v.y);
                o.z = (1.0f - zz.z) * ss.z + zz.z * tanhf(f.z + v.z);
                o.w = (1.0f - zz.w) * ss.w + zz.w * tanhf(f.w + v.w);
                if (r == 0) o = make_float4(0.f, 0.f, 0.f, 0.f);
                *(float4*)&dst[(size_t)r * 256 + c] = o;
            }
        }
    }
}

// ---------------- qscore: per-row reduce of lrelu(Q)·alpha[:, :64] ----------
__global__ void qscore_kernel(const float* __restrict__ alpha) {
    int warp = threadIdx.x >> 5, lane = threadIdx.x & 31;
    int n = blockIdx.x * 8 + warp;
    float acc[4] = {0.f, 0.f, 0.f, 0.f};
#pragma unroll
    for (int tt = 0; tt < 8; tt++) {
        int c = lane + 32 * tt;
        float v = g_P[(size_t)n * H + c];
        float lr = v >= 0.f ? v : 0.01f * v;
        acc[tt >> 1] += lr * alpha[(tt >> 1) * 128 + (c & 63)];
    }
#pragma unroll
    for (int hh = 0; hh < 4; hh++)
        for (int o = 16; o; o >>= 1)
            acc[hh] += __shfl_xor_sync(0xffffffffu, acc[hh], o);
    if (lane == 0) {
#pragma unroll
        for (int hh = 0; hh < 4; hh++) g_qs[n * 4 + hh] = acc[hh];
    }
}

// ---------------- per-step: kscore (lrelu(K)·alpha[:,64:]) + rowsum(h) ------
__global__ void prep_kernel(const float* __restrict__ alpha) {
    int warp = threadIdx.x >> 5, lane = threadIdx.x & 31;
    int n = blockIdx.x * 8 + warp;
    float rs = 0.f;
    float acc[4] = {0.f, 0.f, 0.f, 0.f};
#pragma unroll
    for (int tt = 0; tt < 8; tt++) {
        int c = lane + 32 * tt;
        rs += g_h[(size_t)n * H + c];
        float v = g_KV[(size_t)n * (2 * H) + c];
        float lr = v >= 0.f ? v : 0.01f * v;
        acc[tt >> 1] += lr * alpha[(tt >> 1) * 128 + 64 + (c & 63)];
    }
    for (int o = 16; o; o >>= 1) {
        rs += __shfl_xor_sync(0xffffffffu, rs, o);
#pragma unroll
        for (int hh = 0; hh < 4; hh++)
            acc[hh] += __shfl_xor_sync(0xffffffffu, acc[hh], o);
    }
    if (lane == 0) {
        g_rowsum[n] = rs;
#pragma unroll
        for (int hh = 0; hh < 4; hh++) g_ks[n * 4 + hh] = acc[hh];
    }
}

// ---------------- attention: scores -> softmax(10) -> weighted V gather -----
__global__ __launch_bounds__(256)
void attn_kernel(const int* __restrict__ bgraph, const float* __restrict__ abias) {
    int n = blockIdx.x;
    int t = threadIdx.x;
    __shared__ int js[NNB];
    __shared__ float sc[NNB][HEADS];
    __shared__ float wgt[NNB][HEADS];
    if (t < NNB) js[t] = bgraph[n * NNB + t];
    __syncthreads();
    if (t < NNB * HEADS) {
        int m = t >> 2, hh = t & 3;
        int j = js[m];
        float s = g_qs[n * 4 + hh] + g_ks[j * 4 + hh] + abias[hh];
        if (g_rowsum[j] == 0.0f) s = NEG_INF;
        sc[m][hh] = s;
    }
    __syncthreads();
    if (t < HEADS) {
        float mx = -INFINITY;
#pragma unroll
        for (int m = 0; m < NNB; m++) mx = fmaxf(mx, sc[m][t]);
        float e[NNB], ssum = 0.f;
#pragma unroll
        for (int m = 0; m < NNB; m++) { e[m] = expf(sc[m][t] - mx); ssum += e[m]; }
        float inv = 1.0f / ssum;
#pragma unroll
        for (int m = 0; m < NNB; m++) wgt[m][t] = e[m] * inv;
    }
    __syncthreads();
    int hh = t >> 6;
    float acc = 0.f;
#pragma unroll
    for (int m = 0; m < NNB; m++)
        acc += wgt[m][hh] * g_KV[(size_t)js[m] * (2 * H) + H + t];
    g_sumh[(size_t)n * H + t] = acc;
}

// ---------------- launch -----------------------------------------------------
static float* symaddr(const void* s) {
    void* p = nullptr;
    cudaGetSymbolAddress(&p, s);
    return (float*)p;
}

extern "C" void kernel_launch(void* const* d_in, const int* in_sizes, int n_in,
                              void* d_out, int out_size) {
    const float* fmess = (const float*)d_in[0];
    const int*   bgraph = (const int*)d_in[1];
    const float* Wq = (const float*)d_in[2];
    const float* bq = (const float*)d_in[3];
    const float* Wk = (const float*)d_in[4];
    const float* bk = (const float*)d_in[5];
    const float* Wv = (const float*)d_in[6];
    const float* bv = (const float*)d_in[7];
    const float* alpha = (const float*)d_in[8];
    const float* abias = (const float*)d_in[9];
    const float* Wz = (const float*)d_in[10];
    const float* bz = (const float*)d_in[11];
    const float* Wr = (const float*)d_in[12];
    const float* Ur = (const float*)d_in[13];
    const float* bur = (const float*)d_in[14];
    const float* Wh = (const float*)d_in[15];
    const float* bh = (const float*)d_in[16];
    float* out = (float*)d_out;

    float* p_h    = symaddr(g_h);
    float* p_KV   = symaddr(g_KV);
    float* p_sumh = symaddr(g_sumh);
    float* p_rs   = symaddr(g_rs);
    float* p_F    = symaddr(g_F);
    float* p_P    = symaddr(g_P);
    float* p_fpad = symaddr(g_fpad);
    float* p_Wkv  = symaddr(g_Wkv);
    float* p_Wzr  = symaddr(g_Wzr);
    float* p_Wh2  = symaddr(g_Wh2);
    float* p_Wf   = symaddr(g_Wf);
    float* p_Wqp  = symaddr(g_Wqp);
    float* p_bkv  = symaddr(g_bkv);
    float* p_bf   = symaddr(g_bf);

    cudaMemsetAsync(p_h, 0, (size_t)N_MSG * H * sizeof(float), 0);

    pad_fmess<<<(N_MSG * KPAD + 255) / 256, 256>>>(fmess);
    // pack covers max(H*2*H, KPAD*3*H) = 131072 elements -> 512 blocks
    pack_all<<<512, 256>>>(Wq, Wk, bk, Wv, bv, Wz, bz, Wr, Ur, bur, Wh, bh);

    // loop-invariant: F = fmess @ [Wz1|Wr|Wh1]^T + [bz|bur|bh]   (K padded to 144)
    gemm128<<<dim3(768 / BN, N_MSG / BM), 256>>>(p_fpad, KPAD, p_Wf, 768, p_bf,
                                                 p_F, KPAD, MODE_PLAIN, nullptr);
    // Q = fmess @ Wq^T + bq -> g_P, then reduce to qscore
    gemm128<<<dim3(256 / BN, N_MSG / BM), 256>>>(p_fpad, KPAD, p_Wqp, 256, bq,
                                                 p_P, KPAD, MODE_PLAIN, nullptr);
    qscore_kernel<<<N_MSG / 8, 256>>>(alpha);

    for (int step = 0; step < DEPTH; step++) {
        // K|V = h @ [Wk|Wv]^T + [bk|bv]
        gemm128<<<dim3(512 / BN, N_MSG / BM), 256>>>(p_h, H, p_Wkv, 512, p_bkv,
                                                     p_KV, H, MODE_PLAIN, nullptr);
        prep_kernel<<<N_MSG / 8, 256>>>(alpha);
        attn_kernel<<<N_MSG, 256>>>(bgraph, abias);
        // fused: [z | r*sum_h] from sum_h @ [Wz2|Ur]^T
        gemm128<<<dim3(512 / BN, N_MSG / BM), 256>>>(p_sumh, H, p_Wzr, 512, nullptr,
                                                     nullptr, H, MODE_ZR, nullptr);
        // fused final: new_h = (1-z)*sum_h + z*tanh(Fh + rs@Wh2^T), masked row 0
        gemm128<<<dim3(256 / BN, N_MSG / BM), 256>>>(p_rs, H, p_Wh2, 256, nullptr,
                                                     nullptr, H, MODE_FINAL,
                                                     step == DEPTH - 1 ? out : p_h);
    }
    (void)in_sizes; (void)n_in; (void)out_size;
}

// round 5
// speedup vs baseline: 1.7558x; 1.2217x over previous
#include <cuda_runtime.h>
#include <cuda_bf16.h>
#include <cstdint>

#define N_MSG 16384
#define NNB 10
#define IN_F 135
#define KQ 192            // padded fmess K (multiple of 32)
#define H 256
#define HEADS 4
#define DEPTH 5
#define NEG_INF -1e18f

// ---------------- fp32 state ------------------------------------------------
__device__ float g_h[N_MSG * H];
__device__ float g_KV[N_MSG * 2 * H];
__device__ float g_sumh[N_MSG * H];
__device__ float g_z[N_MSG * H];
__device__ float g_F[N_MSG * 3 * H];
__device__ float g_P[N_MSG * H];
__device__ float g_qs[N_MSG * HEADS];
__device__ float g_ks[N_MSG * HEADS];
__device__ float g_rowsum[N_MSG];
// ---------------- bf16 hi/lo GEMM operands ----------------------------------
__device__ __align__(16) __nv_bfloat16 g_h16h[N_MSG * H], g_h16l[N_MSG * H];
__device__ __align__(16) __nv_bfloat16 g_sh16h[N_MSG * H], g_sh16l[N_MSG * H];
__device__ __align__(16) __nv_bfloat16 g_rs16h[N_MSG * H], g_rs16l[N_MSG * H];
__device__ __align__(16) __nv_bfloat16 g_f16h[N_MSG * KQ], g_f16l[N_MSG * KQ];
__device__ __align__(16) __nv_bfloat16 g_Wkvh[512 * H], g_Wkvl[512 * H];
__device__ __align__(16) __nv_bfloat16 g_Wzrh[512 * H], g_Wzrl[512 * H];
__device__ __align__(16) __nv_bfloat16 g_Wh2h[H * H], g_Wh2l[H * H];
__device__ __align__(16) __nv_bfloat16 g_Wpreh[1024 * KQ], g_Wprel[1024 * KQ];
__device__ float g_bkv[512];
__device__ float g_bpre[1024];

// ---------------- helpers ----------------------------------------------------
__device__ __forceinline__ void split_bf16(float x, __nv_bfloat16& hi, __nv_bfloat16& lo) {
    hi = __float2bfloat16(x);
    lo = __float2bfloat16(x - __bfloat162float(hi));
}
__device__ __forceinline__ float sigmoidf_(float x) { return 1.0f / (1.0f + expf(-x)); }

__device__ __forceinline__ uint32_t smem_u32(const void* p) {
    uint32_t a;
    asm("{ .reg .u64 t; cvta.to.shared.u64 t, %1; cvt.u32.u64 %0, t; }" : "=r"(a) : "l"(p));
    return a;
}
__device__ __forceinline__ void ldsm_x4(uint32_t& r0, uint32_t& r1, uint32_t& r2,
                                        uint32_t& r3, uint32_t addr) {
    asm volatile("ldmatrix.sync.aligned.m8n8.x4.shared.b16 {%0,%1,%2,%3}, [%4];"
                 : "=r"(r0), "=r"(r1), "=r"(r2), "=r"(r3) : "r"(addr));
}
__device__ __forceinline__ void mma16816(float* d, const uint32_t* a, const uint32_t* b) {
    asm volatile(
        "mma.sync.aligned.m16n8k16.row.col.f32.bf16.bf16.f32 "
        "{%0,%1,%2,%3}, {%4,%5,%6,%7}, {%8,%9}, {%0,%1,%2,%3};"
        : "+f"(d[0]), "+f"(d[1]), "+f"(d[2]), "+f"(d[3])
        : "r"(a[0]), "r"(a[1]), "r"(a[2]), "r"(a[3]), "r"(b[0]), "r"(b[1]));
}

// ---------------- pad/split fmess -------------------------------------------
__global__ void pad_fmess(const float* __restrict__ fmess) {
    int i = blockIdx.x * blockDim.x + threadIdx.x;
    if (i >= N_MSG * KQ) return;
    int n = i / KQ, c = i % KQ;
    float x = (c < IN_F) ? fmess[n * IN_F + c] : 0.0f;
    split_bf16(x, g_f16h[i], g_f16l[i]);
}

// ---------------- weight packing --------------------------------------------
__global__ void pack_all(const float* __restrict__ Wq, const float* __restrict__ bq,
                         const float* __restrict__ Wk, const float* __restrict__ bk,
                         const float* __restrict__ Wv, const float* __restrict__ bv,
                         const float* __restrict__ Wz, const float* __restrict__ bz,
                         const float* __restrict__ Wr, const float* __restrict__ Ur,
                         const float* __restrict__ bur,
                         const float* __restrict__ Wh, const float* __restrict__ bh) {
    int i = blockIdx.x * blockDim.x + threadIdx.x;
    const int WIDE = IN_F + H;  // 391
    if (i < 512 * H) {
        int n = i / H, k = i % H;
        float kv = (n < H) ? Wk[n * H + k] : Wv[(n - H) * H + k];
        split_bf16(kv, g_Wkvh[i], g_Wkvl[i]);
        float zr = (n < H) ? Wz[n * WIDE + IN_F + k] : Ur[(n - H) * H + k];
        split_bf16(zr, g_Wzrh[i], g_Wzrl[i]);
    }
    if (i < H * H) {
        int n = i / H, k = i % H;
        split_bf16(Wh[n * WIDE + IN_F + k], g_Wh2h[i], g_Wh2l[i]);
    }
    if (i < 1024 * KQ) {
        int n = i / KQ, k = i % KQ;
        float v = 0.0f;
        if (k < IN_F) {
            if (n < 256) v = Wz[n * WIDE + k];
            else if (n < 512) v = Wr[(n - 256) * IN_F + k];
            else if (n < 768) v = Wh[(n - 512) * WIDE + k];
            else v = Wq[(n - 768) * IN_F + k];
        }
        split_bf16(v, g_Wpreh[i], g_Wprel[i]);
    }
    if (i < 512) g_bkv[i] = (i < 256) ? bk[i] : bv[i - 256];
    if (i < 1024) {
        float b = (i < 256) ? bz[i] : (i < 512) ? bur[i - 256]
                : (i < 768) ? bh[i - 512] : bq[i - 768];
        g_bpre[i] = b;
    }
}

// ---------------- mma.sync GEMM: 128x128 tile, 3-term split-bf16 -------------
#define GT_PRE 0
#define GT_KV 1
#define GT_ZR 2
#define GT_FINAL 3
#define STR 40   // padded smem row stride (bf16 units); 80B -> ldmatrix conflict-free

__global__ __launch_bounds__(256)
void gemm_mma(const __nv_bfloat16* __restrict__ Ah, const __nv_bfloat16* __restrict__ Al,
              const __nv_bfloat16* __restrict__ Bh, const __nv_bfloat16* __restrict__ Bl,
              const float* __restrict__ bias, int Kp, int mode, float* __restrict__ dst) {
    __shared__ __nv_bfloat16 As[2][128 * STR];
    __shared__ __nv_bfloat16 Bs[2][128 * STR];

    const int tid = threadIdx.x, lane = tid & 31, wid = tid >> 5;
    const int wm = (wid & 1) * 64, wn = (wid >> 1) * 32;
    const int row0 = blockIdx.y * 128, col0 = blockIdx.x * 128;

    // gmem->smem mapping: 2 uint4 per thread per array
    const int grow = tid >> 2, gj = (tid & 3) << 3;      // row 0..63, col j*8
    // ldmatrix base addresses (per buffer)
    uint32_t sAb[2], sBb[2];
    {
        int arow = wm + (lane & 15);
        int ak = (lane >> 4) << 3;
        int g = lane >> 3;
        int brow = wn + ((g >> 1) << 3) + (lane & 7);
        int bk = (g & 1) << 3;
        for (int b = 0; b < 2; b++) {
            sAb[b] = smem_u32(&As[b][0]) + (arow * STR + ak) * 2;
            sBb[b] = smem_u32(&Bs[b][0]) + (brow * STR + bk) * 2;
        }
    }

    const int cpp = Kp >> 5;        // 32-wide chunks per phase
    const int NC = 3 * cpp;

    float acc[4][4][4];
#pragma unroll
    for (int i = 0; i < 4; i++)
#pragma unroll
        for (int j = 0; j < 4; j++)
#pragma unroll
            for (int q = 0; q < 4; q++) acc[i][j][q] = 0.f;

    auto seg = [&](int c, const __nv_bfloat16*& Aseg, const __nv_bfloat16*& Bseg, int& kk) {
        int p = c / cpp;
        kk = (c - p * cpp) << 5;
        Aseg = (p < 2) ? Ah : Al;   // [hi, hi, lo]
        Bseg = (p == 1) ? Bl : Bh;  // [hi, lo, hi]
    };

    uint4 ra[2], rb[2];
    {   // fill chunk 0
        const __nv_bfloat16 *Aseg, *Bseg; int kk;
        seg(0, Aseg, Bseg, kk);
#pragma unroll
        for (int i = 0; i < 2; i++) {
            int r = grow + i * 64;
            ra[i] = *(const uint4*)(Aseg + (size_t)(row0 + r) * Kp + kk + gj);
            rb[i] = *(const uint4*)(Bseg + (size_t)(col0 + r) * Kp + kk + gj);
            *(uint4*)(&As[0][r * STR + gj]) = ra[i];
            *(uint4*)(&Bs[0][r * STR + gj]) = rb[i];
        }
    }
    __syncthreads();

    for (int c = 0; c < NC; c++) {
        const int b = c & 1;
        if (c + 1 < NC) {
            const __nv_bfloat16 *Aseg, *Bseg; int kk;
            seg(c + 1, Aseg, Bseg, kk);
#pragma unroll
            for (int i = 0; i < 2; i++) {
                int r = grow + i * 64;
                ra[i] = *(const uint4*)(Aseg + (size_t)(row0 + r) * Kp + kk + gj);
                rb[i] = *(const uint4*)(Bseg + (size_t)(col0 + r) * Kp + kk + gj);
            }
        }
        // compute chunk c: 2 k16 steps
#pragma unroll
        for (int kk2 = 0; kk2 < 2; kk2++) {
            uint32_t a[4][4], bf[4][2];
#pragma unroll
            for (int mt = 0; mt < 4; mt++)
                ldsm_x4(a[mt][0], a[mt][1], a[mt][2], a[mt][3],
                        sAb[b] + mt * 16 * STR * 2 + kk2 * 32);
#pragma unroll
            for (int np = 0; np < 2; np++)
                ldsm_x4(bf[2 * np][0], bf[2 * np][1], bf[2 * np + 1][0], bf[2 * np + 1][1],
                        sBb[b] + np * 16 * STR * 2 + kk2 * 32);
#pragma unroll
            for (int mt = 0; mt < 4; mt++)
#pragma unroll
                for (int nt = 0; nt < 4; nt++)
                    mma16816(acc[mt][nt], a[mt], bf[nt]);
        }
        if (c + 1 < NC) {
            const int nb = b ^ 1;
#pragma unroll
            for (int i = 0; i < 2; i++) {
                int r = grow + i * 64;
                *(uint4*)(&As[nb][r * STR + gj]) = ra[i];
                *(uint4*)(&Bs[nb][r * STR + gj]) = rb[i];
            }
            __syncthreads();
        }
    }

    // ---------------- fused epilogue ----------------
    auto apply = [&](int r, int c, float v0, float v1) {
        if (mode == GT_PRE) {
            v0 += bias[c]; v1 += bias[c + 1];
            if (c < 768) {
                g_F[(size_t)r * 768 + c] = v0;
                g_F[(size_t)r * 768 + c + 1] = v1;
            } else {
                g_P[(size_t)r * 256 + c - 768] = v0;
                g_P[(size_t)r * 256 + c - 767] = v1;
            }
        } else if (mode == GT_KV) {
            dst[(size_t)r * 512 + c] = v0 + bias[c];
            dst[(size_t)r * 512 + c + 1] = v1 + bias[c + 1];
        } else if (mode == GT_ZR) {
            if (c < 256) {
                g_z[(size_t)r * 256 + c] = sigmoidf_(g_F[(size_t)r * 768 + c] + v0);
                g_z[(size_t)r * 256 + c + 1] = sigmoidf_(g_F[(size_t)r * 768 + c + 1] + v1);
            } else {
                int cc = c - 256;
                float rv0 = sigmoidf_(g_F[(size_t)r * 768 + 256 + cc] + v0) *
                            g_sumh[(size_t)r * 256 + cc];
                float rv1 = sigmoidf_(g_F[(size_t)r * 768 + 257 + cc] + v1) *
                            g_sumh[(size_t)r * 256 + cc + 1];
                split_bf16(rv0, g_rs16h[(size_t)r * 256 + cc], g_rs16l[(size_t)r * 256 + cc]);
                split_bf16(rv1, g_rs16h[(size_t)r * 256 + cc + 1], g_rs16l[(size_t)r * 256 + cc + 1]);
            }
        } else {  // GT_FINAL
            float pre0 = tanhf(g_F[(size_t)r * 768 + 512 + c] + v0);
            float pre1 = tanhf(g_F[(size_t)r * 768 + 513 + c] + v1);
            float z0 = g_z[(size_t)r * 256 + c], z1 = g_z[(size_t)r * 256 + c + 1];
            float s0 = g_sumh[(size_t)r * 256 + c], s1 = g_sumh[(size_t)r * 256 + c + 1];
            float nh0 = (1.0f - z0) * s0 + z0 * pre0;
            float nh1 = (1.0f - z1) * s1 + z1 * pre1;
            if (r == 0) { nh0 = 0.0f; nh1 = 0.0f; }
            dst[(size_t)r * 256 + c] = nh0;
            dst[(size_t)r * 256 + c + 1] = nh1;
            split_bf16(nh0, g_h16h[(size_t)r * 256 + c], g_h16l[(size_t)r * 256 + c]);
            split_bf16(nh1, g_h16h[(size_t)r * 256 + c + 1], g_h16l[(size_t)r * 256 + c + 1]);
        }
    };

#pragma unroll
    for (int mt = 0; mt < 4; mt++) {
#pragma unroll
        for (int nt = 0; nt < 4; nt++) {
            int r = row0 + wm + mt * 16 + (lane >> 2);
            int c = col0 + wn + nt * 8 + ((lane & 3) << 1);
            apply(r, c, acc[mt][nt][0], acc[mt][nt][1]);
            apply(r + 8, c, acc[mt][nt][2], acc[mt][nt][3]);
        }
    }
}

// ---------------- qscore ------------------------------------------------------
__global__ void qscore_kernel(const float* __restrict__ alpha) {
    int warp = threadIdx.x >> 5, lane = threadIdx.x & 31;
    int n = blockIdx.x * 8 + warp;
    float acc[4] = {0.f, 0.f, 0.f, 0.f};
#pragma unroll
    for (int tt = 0; tt < 8; tt++) {
        int c = lane + 32 * tt;
        float v = g_P[(size_t)n * H + c];
        float lr = v >= 0.f ? v : 0.01f * v;
        acc[tt >> 1] += lr * alpha[(tt >> 1) * 128 + (c & 63)];
    }
#pragma unroll
    for (int hh = 0; hh < 4; hh++)
        for (int o = 16; o; o >>= 1)
            acc[hh] += __shfl_xor_sync(0xffffffffu, acc[hh], o);
    if (lane == 0) {
#pragma unroll
        for (int hh = 0; hh < 4; hh++) g_qs[n * 4 + hh] = acc[hh];
    }
}

// ---------------- per-step: kscore + rowsum(h) -------------------------------
__global__ void prep_kernel(const float* __restrict__ alpha) {
    int warp = threadIdx.x >> 5, lane = threadIdx.x & 31;
    int n = blockIdx.x * 8 + warp;
    float rs = 0.f;
    float acc[4] = {0.f, 0.f, 0.f, 0.f};
#pragma unroll
    for (int tt = 0; tt < 8; tt++) {
        int c = lane + 32 * tt;
        rs += g_h[(size_t)n * H + c];
        float v = g_KV[(size_t)n * 512 + c];
        float lr = v >= 0.f ? v : 0.01f * v;
        acc[tt >> 1] += lr * alpha[(tt >> 1) * 128 + 64 + (c & 63)];
    }
    for (int o = 16; o; o >>= 1) {
        rs += __shfl_xor_sync(0xffffffffu, rs, o);
#pragma unroll
        for (int hh = 0; hh < 4; hh++)
            acc[hh] += __shfl_xor_sync(0xffffffffu, acc[hh], o);
    }
    if (lane == 0) {
        g_rowsum[n] = rs;
#pragma unroll
        for (int hh = 0; hh < 4; hh++) g_ks[n * 4 + hh] = acc[hh];
    }
}

// ---------------- attention ---------------------------------------------------
__global__ __launch_bounds__(256)
void attn_kernel(const int* __restrict__ bgraph, const float* __restrict__ abias) {
    int n = blockIdx.x;
    int t = threadIdx.x;
    __shared__ int js[NNB];
    __shared__ float sc[NNB][HEADS];
    __shared__ float wgt[NNB][HEADS];
    if (t < NNB) js[t] = bgraph[n * NNB + t];
    __syncthreads();
    if (t < NNB * HEADS) {
        int m = t >> 2, hh = t & 3;
        int j = js[m];
        float s = g_qs[n * 4 + hh] + g_ks[j * 4 + hh] + abias[hh];
        if (g_rowsum[j] == 0.0f) s = NEG_INF;
        sc[m][hh] = s;
    }
    __syncthreads();
    if (t < HEADS) {
        float mx = -INFINITY;
#pragma unroll
        for (int m = 0; m < NNB; m++) mx = fmaxf(mx, sc[m][t]);
        float e[NNB], ssum = 0.f;
#pragma unroll
        for (int m = 0; m < NNB; m++) { e[m] = expf(sc[m][t] - mx); ssum += e[m]; }
        float inv = 1.0f / ssum;
#pragma unroll
        for (int m = 0; m < NNB; m++) wgt[m][t] = e[m] * inv;
    }
    __syncthreads();
    int hh = t >> 6;
    float acc = 0.f;
#pragma unroll
    for (int m = 0; m < NNB; m++)
        acc += wgt[m][hh] * g_KV[(size_t)js[m] * 512 + 256 + t];
    size_t idx = (size_t)n * H + t;
    g_sumh[idx] = acc;
    split_bf16(acc, g_sh16h[idx], g_sh16l[idx]);
}

// ---------------- launch -------------------------------------------------------
static void* symaddr(const void* s) {
    void* p = nullptr;
    cudaGetSymbolAddress(&p, s);
    return p;
}

extern "C" void kernel_launch(void* const* d_in, const int* in_sizes, int n_in,
                              void* d_out, int out_size) {
    const float* fmess = (const float*)d_in[0];
    const int*   bgraph = (const int*)d_in[1];
    const float* Wq = (const float*)d_in[2];
    const float* bq = (const float*)d_in[3];
    const float* Wk = (const float*)d_in[4];
    const float* bk = (const float*)d_in[5];
    const float* Wv = (const float*)d_in[6];
    const float* bv = (const float*)d_in[7];
    const float* alpha = (const float*)d_in[8];
    const float* abias = (const float*)d_in[9];
    const float* Wz = (const float*)d_in[10];
    const float* bz = (const float*)d_in[11];
    const float* Wr = (const float*)d_in[12];
    const float* Ur = (const float*)d_in[13];
    const float* bur = (const float*)d_in[14];
    const float* Wh = (const float*)d_in[15];
    const float* bh = (const float*)d_in[16];
    float* out = (float*)d_out;

    float* p_h    = (float*)symaddr(g_h);
    float* p_KV   = (float*)symaddr(g_KV);
    void*  p_h16h = symaddr(g_h16h);
    void*  p_h16l = symaddr(g_h16l);
    const __nv_bfloat16* a_h16h = (const __nv_bfloat16*)p_h16h;
    const __nv_bfloat16* a_h16l = (const __nv_bfloat16*)p_h16l;
    const __nv_bfloat16* a_sh_h = (const __nv_bfloat16*)symaddr(g_sh16h);
    const __nv_bfloat16* a_sh_l = (const __nv_bfloat16*)symaddr(g_sh16l);
    const __nv_bfloat16* a_rs_h = (const __nv_bfloat16*)symaddr(g_rs16h);
    const __nv_bfloat16* a_rs_l = (const __nv_bfloat16*)symaddr(g_rs16l);
    const __nv_bfloat16* a_f_h  = (const __nv_bfloat16*)symaddr(g_f16h);
    const __nv_bfloat16* a_f_l  = (const __nv_bfloat16*)symaddr(g_f16l);
    const __nv_bfloat16* w_kv_h = (const __nv_bfloat16*)symaddr(g_Wkvh);
    const __nv_bfloat16* w_kv_l = (const __nv_bfloat16*)symaddr(g_Wkvl);
    const __nv_bfloat16* w_zr_h = (const __nv_bfloat16*)symaddr(g_Wzrh);
    const __nv_bfloat16* w_zr_l = (const __nv_bfloat16*)symaddr(g_Wzrl);
    const __nv_bfloat16* w_h2_h = (const __nv_bfloat16*)symaddr(g_Wh2h);
    const __nv_bfloat16* w_h2_l = (const __nv_bfloat16*)symaddr(g_Wh2l);
    const __nv_bfloat16* w_pr_h = (const __nv_bfloat16*)symaddr(g_Wpreh);
    const __nv_bfloat16* w_pr_l = (const __nv_bfloat16*)symaddr(g_Wprel);
    const float* b_kv  = (const float*)symaddr(g_bkv);
    const float* b_pre = (const float*)symaddr(g_bpre);

    cudaMemsetAsync(p_h, 0, (size_t)N_MSG * H * sizeof(float), 0);
    cudaMemsetAsync(p_h16h, 0, (size_t)N_MSG * H * sizeof(__nv_bfloat16), 0);
    cudaMemsetAsync(p_h16l, 0, (size_t)N_MSG * H * sizeof(__nv_bfloat16), 0);

    pad_fmess<<<(N_MSG * KQ + 255) / 256, 256>>>(fmess);
    pack_all<<<(1024 * KQ + 255) / 256, 256>>>(Wq, bq, Wk, bk, Wv, bv, Wz, bz,
                                               Wr, Ur, bur, Wh, bh);

    // PRE: [F(768) | Qpre(256)] = fmess @ Wpre^T + bpre   (K=192, 3-term bf16)
    gemm_mma<<<dim3(8, 128), 256>>>(a_f_h, a_f_l, w_pr_h, w_pr_l,
                                    b_pre, KQ, GT_PRE, nullptr);
    qscore_kernel<<<N_MSG / 8, 256>>>(alpha);

    for (int step = 0; step < DEPTH; step++) {
        gemm_mma<<<dim3(4, 128), 256>>>(a_h16h, a_h16l, w_kv_h, w_kv_l,
                                        b_kv, H, GT_KV, p_KV);
        prep_kernel<<<N_MSG / 8, 256>>>(alpha);
        attn_kernel<<<N_MSG, 256>>>(bgraph, abias);
        gemm_mma<<<dim3(4, 128), 256>>>(a_sh_h, a_sh_l, w_zr_h, w_zr_l,
                                        nullptr, H, GT_ZR, nullptr);
        gemm_mma<<<dim3(2, 128), 256>>>(a_rs_h, a_rs_l, w_h2_h, w_h2_l,
                                        nullptr, H, GT_FINAL,
                                        step == DEPTH - 1 ? out : p_h);
    }
    (void)in_sizes; (void)n_in; (void)out_size;
}

// round 6
// speedup vs baseline: 1.9945x; 1.1359x over previous
#include <cuda_runtime.h>
#include <cuda_bf16.h>
#include <cstdint>

#define N_MSG 16384
#define NNB 10
#define IN_F 135
#define KQ 192            // padded fmess K (multiple of 32)
#define H 256
#define HEADS 4
#define DEPTH 5
#define NEG_INF -1e18f

// ---------------- fp32 state ------------------------------------------------
__device__ float g_h[N_MSG * H];
__device__ float g_KV[N_MSG * 2 * H];
__device__ float g_sumh[N_MSG * H];
__device__ float g_z[N_MSG * H];
__device__ float g_F[N_MSG * 3 * H];
__device__ float g_P[N_MSG * H];
__device__ float g_qs[N_MSG * HEADS];
__device__ float g_ks[N_MSG * HEADS];
__device__ float g_rowsum[N_MSG];
// ---------------- bf16 hi/lo GEMM operands ----------------------------------
__device__ __align__(16) __nv_bfloat16 g_h16h[N_MSG * H], g_h16l[N_MSG * H];
__device__ __align__(16) __nv_bfloat16 g_sh16h[N_MSG * H], g_sh16l[N_MSG * H];
__device__ __align__(16) __nv_bfloat16 g_rs16h[N_MSG * H], g_rs16l[N_MSG * H];
__device__ __align__(16) __nv_bfloat16 g_f16h[N_MSG * KQ], g_f16l[N_MSG * KQ];
__device__ __align__(16) __nv_bfloat16 g_Wkvh[512 * H], g_Wkvl[512 * H];
__device__ __align__(16) __nv_bfloat16 g_Wzrh[512 * H], g_Wzrl[512 * H];
__device__ __align__(16) __nv_bfloat16 g_Wh2h[H * H], g_Wh2l[H * H];
__device__ __align__(16) __nv_bfloat16 g_Wpreh[1024 * KQ], g_Wprel[1024 * KQ];
__device__ float g_bkv[512];
__device__ float g_bpre[1024];

// ---------------- helpers ----------------------------------------------------
__device__ __forceinline__ void split_bf16(float x, __nv_bfloat16& hi, __nv_bfloat16& lo) {
    hi = __float2bfloat16(x);
    lo = __float2bfloat16(x - __bfloat162float(hi));
}
__device__ __forceinline__ float sigmoidf_(float x) { return 1.0f / (1.0f + expf(-x)); }

__device__ __forceinline__ uint32_t smem_u32(const void* p) {
    uint32_t a;
    asm("{ .reg .u64 t; cvta.to.shared.u64 t, %1; cvt.u32.u64 %0, t; }" : "=r"(a) : "l"(p));
    return a;
}
__device__ __forceinline__ void ldsm_x4(uint32_t& r0, uint32_t& r1, uint32_t& r2,
                                        uint32_t& r3, uint32_t addr) {
    asm volatile("ldmatrix.sync.aligned.m8n8.x4.shared.b16 {%0,%1,%2,%3}, [%4];"
                 : "=r"(r0), "=r"(r1), "=r"(r2), "=r"(r3) : "r"(addr));
}
__device__ __forceinline__ void mma16816(float* d, const uint32_t* a, const uint32_t* b) {
    asm volatile(
        "mma.sync.aligned.m16n8k16.row.col.f32.bf16.bf16.f32 "
        "{%0,%1,%2,%3}, {%4,%5,%6,%7}, {%8,%9}, {%0,%1,%2,%3};"
        : "+f"(d[0]), "+f"(d[1]), "+f"(d[2]), "+f"(d[3])
        : "r"(a[0]), "r"(a[1]), "r"(a[2]), "r"(a[3]), "r"(b[0]), "r"(b[1]));
}
#define CP16(dst, src) \
    asm volatile("cp.async.cg.shared.global [%0], [%1], 16;" :: "r"(dst), "l"(src))
#define CP_COMMIT() asm volatile("cp.async.commit_group;" ::: "memory")
#define CP_WAIT(n)  asm volatile("cp.async.wait_group %0;" :: "n"(n) : "memory")

// ---------------- pad/split fmess -------------------------------------------
__global__ void pad_fmess(const float* __restrict__ fmess) {
    int i = blockIdx.x * blockDim.x + threadIdx.x;
    if (i >= N_MSG * KQ) return;
    int n = i / KQ, c = i % KQ;
    float x = (c < IN_F) ? fmess[n * IN_F + c] : 0.0f;
    split_bf16(x, g_f16h[i], g_f16l[i]);
}

// ---------------- weight packing --------------------------------------------
__global__ void pack_all(const float* __restrict__ Wq, const float* __restrict__ bq,
                         const float* __restrict__ Wk, const float* __restrict__ bk,
                         const float* __restrict__ Wv, const float* __restrict__ bv,
                         const float* __restrict__ Wz, const float* __restrict__ bz,
                         const float* __restrict__ Wr, const float* __restrict__ Ur,
                         const float* __restrict__ bur,
                         const float* __restrict__ Wh, const float* __restrict__ bh) {
    int i = blockIdx.x * blockDim.x + threadIdx.x;
    const int WIDE = IN_F + H;  // 391
    if (i < 512 * H) {
        int n = i / H, k = i % H;
        float kv = (n < H) ? Wk[n * H + k] : Wv[(n - H) * H + k];
        split_bf16(kv, g_Wkvh[i], g_Wkvl[i]);
        float zr = (n < H) ? Wz[n * WIDE + IN_F + k] : Ur[(n - H) * H + k];
        split_bf16(zr, g_Wzrh[i], g_Wzrl[i]);
    }
    if (i < H * H) {
        int n = i / H, k = i % H;
        split_bf16(Wh[n * WIDE + IN_F + k], g_Wh2h[i], g_Wh2l[i]);
    }
    if (i < 1024 * KQ) {
        int n = i / KQ, k = i % KQ;
        float v = 0.0f;
        if (k < IN_F) {
            if (n < 256) v = Wz[n * WIDE + k];
            else if (n < 512) v = Wr[(n - 256) * IN_F + k];
            else if (n < 768) v = Wh[(n - 512) * WIDE + k];
            else v = Wq[(n - 768) * IN_F + k];
        }
        split_bf16(v, g_Wpreh[i], g_Wprel[i]);
    }
    if (i < 512) g_bkv[i] = (i < 256) ? bk[i] : bv[i - 256];
    if (i < 1024) {
        float b = (i < 256) ? bz[i] : (i < 512) ? bur[i - 256]
                : (i < 768) ? bh[i - 512] : bq[i - 768];
        g_bpre[i] = b;
    }
}

// ---------------- mma.sync GEMM: 128x128 tile, 3-term split-bf16 -------------
// 4-stage cp.async pipeline; dynamic smem 80 KB.
#define GT_PRE 0
#define GT_KV 1
#define GT_ZR 2
#define GT_FINAL 3
#define STR 40                  // padded smem row stride (bf16); conflict-free
#define STAGEB (128 * STR * 2)  // 10240 bytes per stage per operand
#define SMEM_DYN (8 * STAGEB)   // 4 stages x (A + B)

__global__ __launch_bounds__(256, 2)
void gemm_mma(const __nv_bfloat16* __restrict__ Ah, const __nv_bfloat16* __restrict__ Al,
              const __nv_bfloat16* __restrict__ Bh, const __nv_bfloat16* __restrict__ Bl,
              const float* __restrict__ bias, int Kp, int mode, float* __restrict__ dst) {
    extern __shared__ __nv_bfloat16 dsm[];
    const uint32_t sA0 = smem_u32(dsm);
    const uint32_t sB0 = sA0 + 4 * STAGEB;

    const int tid = threadIdx.x, lane = tid & 31, wid = tid >> 5;
    const int wm = (wid & 1) * 64, wn = (wid >> 1) * 32;
    const int row0 = blockIdx.y * 128, col0 = blockIdx.x * 128;

    // ldmatrix per-lane offsets (same mapping as validated R5 kernel)
    const int arow = wm + (lane & 15), ak = (lane >> 4) << 3;
    const int g = lane >> 3;
    const int brow = wn + ((g >> 1) << 3) + (lane & 7), bk = (g & 1) << 3;
    const uint32_t aoff_l = (uint32_t)(arow * STR + ak) * 2;
    const uint32_t boff_l = (uint32_t)(brow * STR + bk) * 2;

    // gmem->smem: 2x16B per operand per thread per chunk
    const int grow = tid >> 2, gj = (tid & 3) << 3;

    const int cpp = Kp >> 5;        // 32-wide chunks per phase
    const int NC = 3 * cpp;

    auto seg = [&](int c, const __nv_bfloat16*& Aseg, const __nv_bfloat16*& Bseg, int& kk) {
        int p = c / cpp;
        kk = (c - p * cpp) << 5;
        Aseg = (p < 2) ? Ah : Al;   // [hi, hi, lo]
        Bseg = (p == 1) ? Bl : Bh;  // [hi, lo, hi]
    };
    auto issue = [&](int c) {
        const __nv_bfloat16 *Aseg, *Bseg; int kk;
        seg(c, Aseg, Bseg, kk);
        const uint32_t abase = sA0 + (uint32_t)(c & 3) * STAGEB;
        const uint32_t bbase = sB0 + (uint32_t)(c & 3) * STAGEB;
#pragma unroll
        for (int i = 0; i < 2; i++) {
            int t2 = tid + (i << 8);
            int row = t2 >> 2, coli = (t2 & 3) << 3;
            uint32_t so = (uint32_t)(row * STR + coli) * 2;
            CP16(abase + so, Aseg + (size_t)(row0 + row) * Kp + kk + coli);
            CP16(bbase + so, Bseg + (size_t)(col0 + row) * Kp + kk + coli);
        }
        CP_COMMIT();
    };

    float acc[4][4][4];
#pragma unroll
    for (int i = 0; i < 4; i++)
#pragma unroll
        for (int j = 0; j < 4; j++)
#pragma unroll
            for (int q = 0; q < 4; q++) acc[i][j][q] = 0.f;

    issue(0); issue(1); issue(2);

    for (int c = 0; c < NC; c++) {
        const int allowed = NC - 1 - c;
        if (allowed >= 2)      CP_WAIT(2);
        else if (allowed == 1) CP_WAIT(1);
        else                   CP_WAIT(0);
        __syncthreads();
        if (c + 3 < NC) issue(c + 3);

        const uint32_t abase = sA0 + (uint32_t)(c & 3) * STAGEB + aoff_l;
        const uint32_t bbase = sB0 + (uint32_t)(c & 3) * STAGEB + boff_l;
#pragma unroll
        for (int kk2 = 0; kk2 < 2; kk2++) {
            uint32_t a[4][4], bf[4][2];
#pragma unroll
            for (int mt = 0; mt < 4; mt++)
                ldsm_x4(a[mt][0], a[mt][1], a[mt][2], a[mt][3],
                        abase + mt * 16 * STR * 2 + kk2 * 32);
#pragma unroll
            for (int np = 0; np < 2; np++)
                ldsm_x4(bf[2 * np][0], bf[2 * np][1], bf[2 * np + 1][0], bf[2 * np + 1][1],
                        bbase + np * 16 * STR * 2 + kk2 * 32);
#pragma unroll
            for (int mt = 0; mt < 4; mt++)
#pragma unroll
                for (int nt = 0; nt < 4; nt++)
                    mma16816(acc[mt][nt], a[mt], bf[nt]);
        }
    }

    // ---------------- fused epilogue ----------------
    auto apply = [&](int r, int c, float v0, float v1) {
        if (mode == GT_PRE) {
            v0 += bias[c]; v1 += bias[c + 1];
            if (c < 768) {
                g_F[(size_t)r * 768 + c] = v0;
                g_F[(size_t)r * 768 + c + 1] = v1;
            } else {
                g_P[(size_t)r * 256 + c - 768] = v0;
                g_P[(size_t)r * 256 + c - 767] = v1;
            }
        } else if (mode == GT_KV) {
            dst[(size_t)r * 512 + c] = v0 + bias[c];
            dst[(size_t)r * 512 + c + 1] = v1 + bias[c + 1];
        } else if (mode == GT_ZR) {
            if (c < 256) {
                g_z[(size_t)r * 256 + c] = sigmoidf_(g_F[(size_t)r * 768 + c] + v0);
                g_z[(size_t)r * 256 + c + 1] = sigmoidf_(g_F[(size_t)r * 768 + c + 1] + v1);
            } else {
                int cc = c - 256;
                float rv0 = sigmoidf_(g_F[(size_t)r * 768 + 256 + cc] + v0) *
                            g_sumh[(size_t)r * 256 + cc];
                float rv1 = sigmoidf_(g_F[(size_t)r * 768 + 257 + cc] + v1) *
                            g_sumh[(size_t)r * 256 + cc + 1];
                split_bf16(rv0, g_rs16h[(size_t)r * 256 + cc], g_rs16l[(size_t)r * 256 + cc]);
                split_bf16(rv1, g_rs16h[(size_t)r * 256 + cc + 1], g_rs16l[(size_t)r * 256 + cc + 1]);
            }
        } else {  // GT_FINAL
            float pre0 = tanhf(g_F[(size_t)r * 768 + 512 + c] + v0);
            float pre1 = tanhf(g_F[(size_t)r * 768 + 513 + c] + v1);
            float z0 = g_z[(size_t)r * 256 + c], z1 = g_z[(size_t)r * 256 + c + 1];
            float s0 = g_sumh[(size_t)r * 256 + c], s1 = g_sumh[(size_t)r * 256 + c + 1];
            float nh0 = (1.0f - z0) * s0 + z0 * pre0;
            float nh1 = (1.0f - z1) * s1 + z1 * pre1;
            if (r == 0) { nh0 = 0.0f; nh1 = 0.0f; }
            dst[(size_t)r * 256 + c] = nh0;
            dst[(size_t)r * 256 + c + 1] = nh1;
            split_bf16(nh0, g_h16h[(size_t)r * 256 + c], g_h16l[(size_t)r * 256 + c]);
            split_bf16(nh1, g_h16h[(size_t)r * 256 + c + 1], g_h16l[(size_t)r * 256 + c + 1]);
        }
    };

#pragma unroll
    for (int mt = 0; mt < 4; mt++) {
#pragma unroll
        for (int nt = 0; nt < 4; nt++) {
            int r = row0 + wm + mt * 16 + (lane >> 2);
            int c = col0 + wn + nt * 8 + ((lane & 3) << 1);
            apply(r, c, acc[mt][nt][0], acc[mt][nt][1]);
            apply(r + 8, c, acc[mt][nt][2], acc[mt][nt][3]);
        }
    }
}

// ---------------- qscore ------------------------------------------------------
__global__ void qscore_kernel(const float* __restrict__ alpha) {
    int warp = threadIdx.x >> 5, lane = threadIdx.x & 31;
    int n = blockIdx.x * 8 + warp;
    float acc[4] = {0.f, 0.f, 0.f, 0.f};
#pragma unroll
    for (int tt = 0; tt < 8; tt++) {
        int c = lane + 32 * tt;
        float v = g_P[(size_t)n * H + c];
        float lr = v >= 0.f ? v : 0.01f * v;
        acc[tt >> 1] += lr * alpha[(tt >> 1) * 128 + (c & 63)];
    }
#pragma unroll
    for (int hh = 0; hh < 4; hh++)
        for (int o = 16; o; o >>= 1)
            acc[hh] += __shfl_xor_sync(0xffffffffu, acc[hh], o);
    if (lane == 0) {
#pragma unroll
        for (int hh = 0; hh < 4; hh++) g_qs[n * 4 + hh] = acc[hh];
    }
}

// ---------------- per-step: kscore + rowsum(h) -------------------------------
__global__ void prep_kernel(const float* __restrict__ alpha) {
    int warp = threadIdx.x >> 5, lane = threadIdx.x & 31;
    int n = blockIdx.x * 8 + warp;
    float rs = 0.f;
    float acc[4] = {0.f, 0.f, 0.f, 0.f};
#pragma unroll
    for (int tt = 0; tt < 8; tt++) {
        int c = lane + 32 * tt;
        rs += g_h[(size_t)n * H + c];
        float v = g_KV[(size_t)n * 512 + c];
        float lr = v >= 0.f ? v : 0.01f * v;
        acc[tt >> 1] += lr * alpha[(tt >> 1) * 128 + 64 + (c & 63)];
    }
    for (int o = 16; o; o >>= 1) {
        rs += __shfl_xor_sync(0xffffffffu, rs, o);
#pragma unroll
        for (int hh = 0; hh < 4; hh++)
            acc[hh] += __shfl_xor_sync(0xffffffffu, acc[hh], o);
    }
    if (lane == 0) {
        g_rowsum[n] = rs;
#pragma unroll
        for (int hh = 0; hh < 4; hh++) g_ks[n * 4 + hh] = acc[hh];
    }
}

// ---------------- attention ---------------------------------------------------
__global__ __launch_bounds__(256)
void attn_kernel(const int* __restrict__ bgraph, const float* __restrict__ abias) {
    int n = blockIdx.x;
    int t = threadIdx.x;
    __shared__ int js[NNB];
    __shared__ float sc[NNB][HEADS];
    __shared__ float wgt[NNB][HEADS];
    if (t < NNB) js[t] = bgraph[n * NNB + t];
    __syncthreads();
    if (t < NNB * HEADS) {
        int m = t >> 2, hh = t & 3;
        int j = js[m];
        float s = g_qs[n * 4 + hh] + g_ks[j * 4 + hh] + abias[hh];
        if (g_rowsum[j] == 0.0f) s = NEG_INF;
        sc[m][hh] = s;
    }
    __syncthreads();
    if (t < HEADS) {
        float mx = -INFINITY;
#pragma unroll
        for (int m = 0; m < NNB; m++) mx = fmaxf(mx, sc[m][t]);
        float e[NNB], ssum = 0.f;
#pragma unroll
        for (int m = 0; m < NNB; m++) { e[m] = expf(sc[m][t] - mx); ssum += e[m]; }
        float inv = 1.0f / ssum;
#pragma unroll
        for (int m = 0; m < NNB; m++) wgt[m][t] = e[m] * inv;
    }
    __syncthreads();
    int hh = t >> 6;
    float acc = 0.f;
#pragma unroll
    for (int m = 0; m < NNB; m++)
        acc += wgt[m][hh] * g_KV[(size_t)js[m] * 512 + 256 + t];
    size_t idx = (size_t)n * H + t;
    g_sumh[idx] = acc;
    split_bf16(acc, g_sh16h[idx], g_sh16l[idx]);
}

// ---------------- launch -------------------------------------------------------
static void* symaddr(const void* s) {
    void* p = nullptr;
    cudaGetSymbolAddress(&p, s);
    return p;
}

extern "C" void kernel_launch(void* const* d_in, const int* in_sizes, int n_in,
                              void* d_out, int out_size) {
    const float* fmess = (const float*)d_in[0];
    const int*   bgraph = (const int*)d_in[1];
    const float* Wq = (const float*)d_in[2];
    const float* bq = (const float*)d_in[3];
    const float* Wk = (const float*)d_in[4];
    const float* bk = (const float*)d_in[5];
    const float* Wv = (const float*)d_in[6];
    const float* bv = (const float*)d_in[7];
    const float* alpha = (const float*)d_in[8];
    const float* abias = (const float*)d_in[9];
    const float* Wz = (const float*)d_in[10];
    const float* bz = (const float*)d_in[11];
    const float* Wr = (const float*)d_in[12];
    const float* Ur = (const float*)d_in[13];
    const float* bur = (const float*)d_in[14];
    const float* Wh = (const float*)d_in[15];
    const float* bh = (const float*)d_in[16];
    float* out = (float*)d_out;

    float* p_h    = (float*)symaddr(g_h);
    float* p_KV   = (float*)symaddr(g_KV);
    void*  p_h16h = symaddr(g_h16h);
    void*  p_h16l = symaddr(g_h16l);
    const __nv_bfloat16* a_h16h = (const __nv_bfloat16*)p_h16h;
    const __nv_bfloat16* a_h16l = (const __nv_bfloat16*)p_h16l;
    const __nv_bfloat16* a_sh_h = (const __nv_bfloat16*)symaddr(g_sh16h);
    const __nv_bfloat16* a_sh_l = (const __nv_bfloat16*)symaddr(g_sh16l);
    const __nv_bfloat16* a_rs_h = (const __nv_bfloat16*)symaddr(g_rs16h);
    const __nv_bfloat16* a_rs_l = (const __nv_bfloat16*)symaddr(g_rs16l);
    const __nv_bfloat16* a_f_h  = (const __nv_bfloat16*)symaddr(g_f16h);
    const __nv_bfloat16* a_f_l  = (const __nv_bfloat16*)symaddr(g_f16l);
    const __nv_bfloat16* w_kv_h = (const __nv_bfloat16*)symaddr(g_Wkvh);
    const __nv_bfloat16* w_kv_l = (const __nv_bfloat16*)symaddr(g_Wkvl);
    const __nv_bfloat16* w_zr_h = (const __nv_bfloat16*)symaddr(g_Wzrh);
    const __nv_bfloat16* w_zr_l = (const __nv_bfloat16*)symaddr(g_Wzrl);
    const __nv_bfloat16* w_h2_h = (const __nv_bfloat16*)symaddr(g_Wh2h);
    const __nv_bfloat16* w_h2_l = (const __nv_bfloat16*)symaddr(g_Wh2l);
    const __nv_bfloat16* w_pr_h = (const __nv_bfloat16*)symaddr(g_Wpreh);
    const __nv_bfloat16* w_pr_l = (const __nv_bfloat16*)symaddr(g_Wprel);
    const float* b_kv  = (const float*)symaddr(g_bkv);
    const float* b_pre = (const float*)symaddr(g_bpre);

    cudaFuncSetAttribute(gemm_mma, cudaFuncAttributeMaxDynamicSharedMemorySize, SMEM_DYN);

    cudaMemsetAsync(p_h, 0, (size_t)N_MSG * H * sizeof(float), 0);
    cudaMemsetAsync(p_h16h, 0, (size_t)N_MSG * H * sizeof(__nv_bfloat16), 0);
    cudaMemsetAsync(p_h16l, 0, (size_t)N_MSG * H * sizeof(__nv_bfloat16), 0);

    pad_fmess<<<(N_MSG * KQ + 255) / 256, 256>>>(fmess);
    pack_all<<<(1024 * KQ + 255) / 256, 256>>>(Wq, bq, Wk, bk, Wv, bv, Wz, bz,
                                               Wr, Ur, bur, Wh, bh);

    // PRE: [F(768) | Qpre(256)] = fmess @ Wpre^T + bpre   (K=192, 3-term bf16)
    gemm_mma<<<dim3(8, 128), 256, SMEM_DYN>>>(a_f_h, a_f_l, w_pr_h, w_pr_l,
                                              b_pre, KQ, GT_PRE, nullptr);
    qscore_kernel<<<N_MSG / 8, 256>>>(alpha);

    for (int step = 0; step < DEPTH; step++) {
        gemm_mma<<<dim3(4, 128), 256, SMEM_DYN>>>(a_h16h, a_h16l, w_kv_h, w_kv_l,
                                                  b_kv, H, GT_KV, p_KV);
        prep_kernel<<<N_MSG / 8, 256>>>(alpha);
        attn_kernel<<<N_MSG, 256>>>(bgraph, abias);
        gemm_mma<<<dim3(4, 128), 256, SMEM_DYN>>>(a_sh_h, a_sh_l, w_zr_h, w_zr_l,
                                                  nullptr, H, GT_ZR, nullptr);
        gemm_mma<<<dim3(2, 128), 256, SMEM_DYN>>>(a_rs_h, a_rs_l, w_h2_h, w_h2_l,
                                                  nullptr, H, GT_FINAL,
                                                  step == DEPTH - 1 ? out : p_h);
    }
    (void)in_sizes; (void)n_in; (void)out_size;
}